// round 1
// baseline (speedup 1.0000x reference)
#include <cuda_runtime.h>

#define TOKENS 32768
#define NEXP   64
#define KDIM   2048
#define KC     128      // K-chunk (floats)
#define WST    132      // padded SMEM row stride for W (conflict-free LDS.128)
#define TPB    256      // threads per block (8 warps)
#define TOKB   64       // tokens per block (8 per warp)

typedef unsigned long long u64;

// Packed dual-fp32 FMA (sm_103a FFMA2). Bit-identical to two scalar fp32 FMAs.
__device__ __forceinline__ u64 ffma2(u64 a, u64 b, u64 c) {
    u64 d;
    asm("fma.rn.f32x2 %0, %1, %2, %3;" : "=l"(d) : "l"(a), "l"(b), "l"(c));
    return d;
}
__device__ __forceinline__ float f2lo(u64 v) { return __uint_as_float((unsigned)v); }
__device__ __forceinline__ float f2hi(u64 v) { return __uint_as_float((unsigned)(v >> 32)); }

extern "C" __global__ void __launch_bounds__(TPB)
router_kernel(const float* __restrict__ X, const float* __restrict__ W,
              float* __restrict__ out)
{
    extern __shared__ float smem[];
    float* sW = smem;                  // [64][WST]
    float* sX = smem + NEXP * WST;     // [64][KC]

    const int tid  = threadIdx.x;
    const int warp = tid >> 5;
    const int lane = tid & 31;
    const int tb   = blockIdx.x * TOKB;

    // acc[t][e2]: 8 tokens x 2 experts (lane, lane+32), each an f32x2 pair
    // accumulating even/odd k separately.
    u64 acc[8][2];
    #pragma unroll
    for (int t = 0; t < 8; t++) { acc[t][0] = 0ULL; acc[t][1] = 0ULL; }

    for (int k0 = 0; k0 < KDIM; k0 += KC) {
        // --- stage W chunk [64][KC] into padded SMEM (coalesced float4) ---
        #pragma unroll
        for (int r = 0; r < 8; r++) {
            int i   = tid + r * TPB;        // 0..2047 float4s
            int row = i >> 5;
            int c4  = i & 31;
            float4 v = reinterpret_cast<const float4*>(W + row * KDIM + k0)[c4];
            reinterpret_cast<float4*>(sW + row * WST)[c4] = v;
        }
        // --- stage X chunk [64 tokens][KC] ---
        #pragma unroll
        for (int r = 0; r < 8; r++) {
            int i   = tid + r * TPB;
            int row = i >> 5;
            int c4  = i & 31;
            float4 v = reinterpret_cast<const float4*>(X + (long long)(tb + row) * KDIM + k0)[c4];
            reinterpret_cast<float4*>(sX + row * KC)[c4] = v;
        }
        __syncthreads();

        const ulonglong2* sWu = reinterpret_cast<const ulonglong2*>(sW);
        const ulonglong2* sXu = reinterpret_cast<const ulonglong2*>(sX);
        const int w0base = lane * 33;          // (lane*WST)/4 float4s
        const int w1base = (lane + 32) * 33;
        const int xbase  = (warp * 8) * (KC / 4);

        #pragma unroll 8
        for (int k4 = 0; k4 < KC / 4; k4++) {
            ulonglong2 w0 = sWu[w0base + k4];  // W[lane   ][4k..4k+3] as 2x f32x2
            ulonglong2 w1 = sWu[w1base + k4];  // W[lane+32][4k..4k+3]
            #pragma unroll
            for (int t = 0; t < 8; t++) {
                ulonglong2 xv = sXu[xbase + t * (KC / 4) + k4];  // broadcast
                acc[t][0] = ffma2(xv.x, w0.x, acc[t][0]);
                acc[t][0] = ffma2(xv.y, w0.y, acc[t][0]);
                acc[t][1] = ffma2(xv.x, w1.x, acc[t][1]);
                acc[t][1] = ffma2(xv.y, w1.y, acc[t][1]);
            }
        }
        __syncthreads();
    }

    // Output layout (float32): [indices 32768*2 | weights 32768*2 | logits 32768*64]
    float* outIdx = out;
    float* outWgt = out + TOKENS * 2;
    float* outLog = out + TOKENS * 4;

    #pragma unroll
    for (int t = 0; t < 8; t++) {
        int tok = tb + warp * 8 + t;
        float va = f2lo(acc[t][0]) + f2hi(acc[t][0]);  // expert = lane
        float vb = f2lo(acc[t][1]) + f2hi(acc[t][1]);  // expert = lane+32

        outLog[(long long)tok * NEXP + lane]      = va;
        outLog[(long long)tok * NEXP + lane + 32] = vb;

        // Per-lane top-2 with stable tie-break (lower index wins, matching
        // stable argsort(-scores)).
        float v1, v2; int i1, i2;
        if (vb > va) { v1 = vb; i1 = lane + 32; v2 = va; i2 = lane; }
        else         { v1 = va; i1 = lane;      v2 = vb; i2 = lane + 32; }

        // Warp butterfly merge of sorted top-2 pairs.
        #pragma unroll
        for (int off = 16; off > 0; off >>= 1) {
            float ov1 = __shfl_xor_sync(0xffffffffu, v1, off);
            int   oi1 = __shfl_xor_sync(0xffffffffu, i1, off);
            float ov2 = __shfl_xor_sync(0xffffffffu, v2, off);
            int   oi2 = __shfl_xor_sync(0xffffffffu, i2, off);
            bool mine = (v1 > ov1) || (v1 == ov1 && i1 < oi1);
            float l1v = mine ? ov1 : v1;  int l1i = mine ? oi1 : i1;  // losing top1
            float s2v = mine ? v2  : ov2; int s2i = mine ? i2  : oi2; // winner's #2
            v1 = mine ? v1 : ov1;  i1 = mine ? i1 : oi1;
            bool sec = (s2v > l1v) || (s2v == l1v && s2i < l1i);
            v2 = sec ? s2v : l1v;  i2 = sec ? s2i : l1i;
        }

        if (lane == 0) {
            float e2  = expf(v2 - v1);          // v1 >= v2, stable softmax
            float inv = 1.0f / (1.0f + e2);
            outIdx[tok * 2]     = (float)i1;
            outIdx[tok * 2 + 1] = (float)i2;
            outWgt[tok * 2]     = inv;
            outWgt[tok * 2 + 1] = e2 * inv;
        }
    }
}

extern "C" void kernel_launch(void* const* d_in, const int* in_sizes, int n_in,
                              void* d_out, int out_size)
{
    const float* X = (const float*)d_in[0];   // [32768, 2048] fp32
    const float* W = (const float*)d_in[1];   // [64, 2048] fp32
    float* out = (float*)d_out;

    const int smem_bytes = (NEXP * WST + TOKB * KC) * (int)sizeof(float);  // 66560
    cudaFuncSetAttribute(router_kernel,
                         cudaFuncAttributeMaxDynamicSharedMemorySize, smem_bytes);
    router_kernel<<<TOKENS / TOKB, TPB, smem_bytes>>>(X, W, out);
}

// round 3
// speedup vs baseline: 1.3828x; 1.3828x over previous
#include <cuda_runtime.h>
#include <cstdint>
#include <math.h>

#define TOKENS 32768
#define NEXP   64
#define KDIM   2048
#define KC     32              // floats per K-chunk (4 k8 steps)
#define NCH    (KDIM / KC)     // 64 chunks
#define TILE_M 128
#define TPB    256
#define NKB    (KDIM / 8)      // 256 k8 blocks total

// W pre-split, fragment-ready: [kb(256)][nb(8)][lane(32)] = {b0h, b1h, b0l, b1l}
__device__ float4 g_wperm[NKB * 8 * 32];

static __device__ __forceinline__ float tf32f(float x) {
    uint32_t r;
    asm("cvt.rna.tf32.f32 %0, %1;" : "=r"(r) : "f"(x));
    return __uint_as_float(r);
}
static __device__ __forceinline__ void split2(float v, float& h, float& l) {
    h = tf32f(v);
    l = tf32f(v - h);
}
static __device__ __forceinline__ void mma8(float* d, const uint32_t* a,
                                            uint32_t b0, uint32_t b1) {
    asm volatile(
        "mma.sync.aligned.m16n8k8.row.col.f32.tf32.tf32.f32 "
        "{%0,%1,%2,%3}, {%4,%5,%6,%7}, {%8,%9}, {%0,%1,%2,%3};"
        : "+f"(d[0]), "+f"(d[1]), "+f"(d[2]), "+f"(d[3])
        : "r"(a[0]), "r"(a[1]), "r"(a[2]), "r"(a[3]), "r"(b0), "r"(b1));
}
static __device__ __forceinline__ void merge2(float& v1, int& i1, float& v2, int& i2, int off) {
    float ov1 = __shfl_xor_sync(0xffffffffu, v1, off);
    int   oi1 = __shfl_xor_sync(0xffffffffu, i1, off);
    float ov2 = __shfl_xor_sync(0xffffffffu, v2, off);
    int   oi2 = __shfl_xor_sync(0xffffffffu, i2, off);
    bool mine = (v1 > ov1) || (v1 == ov1 && i1 < oi1);
    float l1v = mine ? ov1 : v1;  int l1i = mine ? oi1 : i1;
    float s2v = mine ? v2  : ov2; int s2i = mine ? i2  : oi2;
    v1 = mine ? v1 : ov1;  i1 = mine ? i1 : oi1;
    bool sec = (s2v > l1v) || (s2v == l1v && s2i < l1i);
    v2 = sec ? s2v : l1v;  i2 = sec ? s2i : l1i;
}

// ---- prep: split W into fragment-ready permuted layout (runs once per launch) ----
extern "C" __global__ void __launch_bounds__(256)
prep_w(const float* __restrict__ W)
{
    int idx  = blockIdx.x * 256 + threadIdx.x;   // 0..65535 = (kb*8+nb)*32+lane
    int lane = idx & 31;
    int nb   = (idx >> 5) & 7;
    int kb   = idx >> 8;
    int g = lane >> 2, t = lane & 3;
    const float* wr = W + (size_t)(nb * 8 + g) * KDIM + kb * 8;
    float4 r;
    split2(wr[t],     r.x, r.z);   // b0: k = t
    split2(wr[t + 4], r.y, r.w);   // b1: k = t+4
    g_wperm[idx] = r;
}

// SMEM (float4 units): per stage 3072 f4 = 48KB:
//   [0..1023]    A-hi  [q(8)][row(128)] (each f4 = 4 consecutive k within q-group)
//   [1024..2047] A-lo
//   [2048..3071] B     [k8(4)][nb(8)][lane(32)]
#define STAGE_F4 3072
#define SMEM_BYTES (2 * STAGE_F4 * 16)   // 98304

extern "C" __global__ void __launch_bounds__(TPB, 2)
router_mma(const float* __restrict__ X, float* __restrict__ out)
{
    extern __shared__ float4 sm4[];
    float*    smf = reinterpret_cast<float*>(sm4);
    const int tid  = threadIdx.x;
    const int wid  = tid >> 5;
    const int lane = tid & 31;
    const int g    = lane >> 2;   // group (row / n)
    const int t    = lane & 3;    // thread-in-group (k / col pair)
    const int blockM = blockIdx.x * TILE_M;

    const bool producer = (wid >= 4);

    if (producer) {
        const int p = tid - 128;                 // 0..127
        float4 xa[8], bb[8];

        // --- helper lambdas (manually inlined as macros via loops) ---
        // load chunk c into regs
        #define PLOAD(c)                                                           \
            {                                                                      \
                _Pragma("unroll")                                                  \
                for (int i = 0; i < 8; i++) {                                      \
                    int row = (p & 7) + 8 * ((p >> 5) & 3) + 32 * (i & 3);         \
                    int q   = ((p >> 3) & 3) + 4 * (i >> 2);                       \
                    xa[i] = *reinterpret_cast<const float4*>(                      \
                        X + (size_t)(blockM + row) * KDIM + (c) * KC + q * 4);     \
                    bb[i] = g_wperm[(c) * 1024 + p + 128 * i];                     \
                }                                                                  \
            }
        // convert + store regs into stage s
        #define PSTORE(s)                                                          \
            {                                                                      \
                float4* aH = sm4 + (s) * STAGE_F4;                                 \
                float4* aL = aH + 1024;                                            \
                float4* sB = aH + 2048;                                            \
                _Pragma("unroll")                                                  \
                for (int i = 0; i < 8; i++) {                                      \
                    int row = (p & 7) + 8 * ((p >> 5) & 3) + 32 * (i & 3);         \
                    int q   = ((p >> 3) & 3) + 4 * (i >> 2);                       \
                    float4 h, l;                                                   \
                    split2(xa[i].x, h.x, l.x);                                     \
                    split2(xa[i].y, h.y, l.y);                                     \
                    split2(xa[i].z, h.z, l.z);                                     \
                    split2(xa[i].w, h.w, l.w);                                     \
                    aH[q * 128 + row] = h;                                         \
                    aL[q * 128 + row] = l;                                         \
                    sB[p + 128 * i]   = bb[i];                                     \
                }                                                                  \
            }

        PLOAD(0);
        PSTORE(0);
        PLOAD(1);
        __syncthreads();

        for (int c = 0; c < NCH; c++) {
            if (c + 1 < NCH) PSTORE((c + 1) & 1);
            if (c + 2 < NCH) PLOAD(c + 2);
            __syncthreads();
        }
        return;   // producers done (no more barriers below)
    }

    // ---------------- consumers: warps 0..3, warp tile m32 x n64 ----------------
    float acc[2][8][4];
    #pragma unroll
    for (int mf = 0; mf < 2; mf++)
        #pragma unroll
        for (int nf = 0; nf < 8; nf++)
            #pragma unroll
            for (int u = 0; u < 4; u++) acc[mf][nf][u] = 0.0f;

    const int wbase = wid * 32;
    __syncthreads();   // matches producers' prologue barrier

    for (int c = 0; c < NCH; c++) {
        const int s = c & 1;
        const uint32_t* aH = reinterpret_cast<const uint32_t*>(smf + s * STAGE_F4 * 4);
        const uint32_t* aL = aH + 4096;
        const float4*   sB = sm4 + s * STAGE_F4 + 2048;

        #pragma unroll
        for (int kb = 0; kb < 4; kb++) {
            uint32_t ah[2][4], al[2][4];
            #pragma unroll
            for (int mf = 0; mf < 2; mf++) {
                const int r0 = wbase + mf * 16 + g;
                const int b  = kb * 1024 + r0 * 4 + t;
                ah[mf][0] = aH[b];            // (row r0,   k=t)
                ah[mf][1] = aH[b + 32];       // (row r0+8, k=t)
                ah[mf][2] = aH[b + 512];      // (row r0,   k=t+4)
                ah[mf][3] = aH[b + 544];      // (row r0+8, k=t+4)
                al[mf][0] = aL[b];
                al[mf][1] = aL[b + 32];
                al[mf][2] = aL[b + 512];
                al[mf][3] = aL[b + 544];
            }
            #pragma unroll
            for (int nf = 0; nf < 8; nf++) {
                float4 bv = sB[(kb * 8 + nf) * 32 + lane];
                uint32_t b0h = __float_as_uint(bv.x), b1h = __float_as_uint(bv.y);
                uint32_t b0l = __float_as_uint(bv.z), b1l = __float_as_uint(bv.w);
                #pragma unroll
                for (int mf = 0; mf < 2; mf++) {
                    mma8(acc[mf][nf], ah[mf], b0h, b1h);   // Ah*Bh
                    mma8(acc[mf][nf], ah[mf], b0l, b1l);   // Ah*Bl
                    mma8(acc[mf][nf], al[mf], b0h, b1h);   // Al*Bh
                }
            }
        }
        __syncthreads();
    }

    // ---------------- epilogue: logits + stable top-2 + softmax ----------------
    float* outIdx = out;
    float* outWgt = out + TOKENS * 2;
    float* outLog = out + TOKENS * 4;

    #pragma unroll
    for (int mf = 0; mf < 2; mf++) {
        #pragma unroll
        for (int h = 0; h < 2; h++) {
            const int row = wbase + mf * 16 + h * 8 + g;
            const int tok = blockM + row;

            float v1 = -INFINITY, v2 = -INFINITY;
            int   i1 = 0, i2 = 0;
            #pragma unroll
            for (int nf = 0; nf < 8; nf++) {
                #pragma unroll
                for (int u = 0; u < 2; u++) {
                    float v  = acc[mf][nf][2 * h + u];
                    int   id = nf * 8 + 2 * t + u;
                    if (v > v1)      { v2 = v1; i2 = i1; v1 = v; i1 = id; }
                    else if (v > v2) { v2 = v;  i2 = id; }
                }
            }
            merge2(v1, i1, v2, i2, 1);
            merge2(v1, i1, v2, i2, 2);

            // logits: this lane owns cols {nf*8 + 2t, +1}
            float* lr = outLog + (size_t)tok * NEXP;
            #pragma unroll
            for (int nf = 0; nf < 8; nf++) {
                float2 o = make_float2(acc[mf][nf][2 * h], acc[mf][nf][2 * h + 1]);
                *reinterpret_cast<float2*>(lr + nf * 8 + 2 * t) = o;
            }

            if (t == 0) {
                float e2  = expf(v2 - v1);          // v1 >= v2 -> stable
                float inv = 1.0f / (1.0f + e2);
                outIdx[tok * 2]     = (float)i1;
                outIdx[tok * 2 + 1] = (float)i2;
                outWgt[tok * 2]     = inv;
                outWgt[tok * 2 + 1] = e2 * inv;
            }
        }
    }
}

extern "C" void kernel_launch(void* const* d_in, const int* in_sizes, int n_in,
                              void* d_out, int out_size)
{
    const float* X = (const float*)d_in[0];   // [32768, 2048] fp32
    const float* W = (const float*)d_in[1];   // [64, 2048] fp32
    float* out = (float*)d_out;

    prep_w<<<NKB, 256>>>(W);

    cudaFuncSetAttribute(router_mma,
                         cudaFuncAttributeMaxDynamicSharedMemorySize, SMEM_BYTES);
    router_mma<<<TOKENS / TILE_M, TPB, SMEM_BYTES>>>(X, out);
}

// round 4
// speedup vs baseline: 2.9085x; 2.1034x over previous
#include <cuda_runtime.h>
#include <cstdint>
#include <math.h>

#define TOKENS 32768
#define NEXP   64
#define KDIM   2048
#define KC     32              // floats per K-chunk (2 k16 steps)
#define NCH    (KDIM / KC)     // 64 chunks
#define TILE_M 128
#define TPB    256
#define NKB16  (KDIM / 16)     // 128 k16 blocks

// W pre-split, fragment-ready bf16: [kb16(128)][nf(8)][lane(32)] = {bh0,bh1,bm0,bm1}
__device__ uint4 g_wperm[NKB16 * 8 * 32];   // 512 KB

static __device__ __forceinline__ uint32_t bfpack(float hi, float lo) {
    uint32_t d;
    asm("cvt.rn.bf16x2.f32 %0, %1, %2;" : "=r"(d) : "f"(hi), "f"(lo));
    return d;
}
static __device__ __forceinline__ float bflo(uint32_t p) { return __uint_as_float(p << 16); }
static __device__ __forceinline__ float bfhi(uint32_t p) { return __uint_as_float(p & 0xFFFF0000u); }

// pack 4 consecutive floats -> (h uint32x? ) produce h-pair and m-pair for 2 floats
static __device__ __forceinline__ void split_pair(float a, float b, uint32_t& h, uint32_t& m) {
    h = bfpack(b, a);                       // lo = a, hi = b
    m = bfpack(b - bfhi(h), a - bflo(h));
}

static __device__ __forceinline__ void mma16(float* d, const uint32_t* a,
                                             uint32_t b0, uint32_t b1) {
    asm volatile(
        "mma.sync.aligned.m16n8k16.row.col.f32.bf16.bf16.f32 "
        "{%0,%1,%2,%3}, {%4,%5,%6,%7}, {%8,%9}, {%0,%1,%2,%3};"
        : "+f"(d[0]), "+f"(d[1]), "+f"(d[2]), "+f"(d[3])
        : "r"(a[0]), "r"(a[1]), "r"(a[2]), "r"(a[3]), "r"(b0), "r"(b1));
}
static __device__ __forceinline__ void merge2(float& v1, int& i1, float& v2, int& i2, int off) {
    float ov1 = __shfl_xor_sync(0xffffffffu, v1, off);
    int   oi1 = __shfl_xor_sync(0xffffffffu, i1, off);
    float ov2 = __shfl_xor_sync(0xffffffffu, v2, off);
    int   oi2 = __shfl_xor_sync(0xffffffffu, i2, off);
    bool mine = (v1 > ov1) || (v1 == ov1 && i1 < oi1);
    float l1v = mine ? ov1 : v1;  int l1i = mine ? oi1 : i1;
    float s2v = mine ? v2  : ov2; int s2i = mine ? i2  : oi2;
    v1 = mine ? v1 : ov1;  i1 = mine ? i1 : oi1;
    bool sec = (s2v > l1v) || (s2v == l1v && s2i < l1i);
    v2 = sec ? s2v : l1v;  i2 = sec ? s2i : l1i;
}

// ---- prep: split W into bf16 fragment-ready layout (once per launch) ----
extern "C" __global__ void __launch_bounds__(256)
prep_w(const float* __restrict__ W)
{
    int idx  = blockIdx.x * 256 + threadIdx.x;  // 0..32767
    int lane = idx & 31;
    int nf   = (idx >> 5) & 7;
    int kb   = idx >> 8;                        // k16 block 0..127
    int g = lane >> 2, t = lane & 3;
    const float* wr = W + (size_t)(nf * 8 + g) * KDIM + kb * 16;
    uint4 r;
    split_pair(wr[2 * t],     wr[2 * t + 1], r.x, r.z);   // b0 (k = 2t, 2t+1)
    split_pair(wr[2 * t + 8], wr[2 * t + 9], r.y, r.w);   // b1 (k = 2t+8, 2t+9)
    g_wperm[idx] = r;
}

// SMEM per stage (uint4 units): aH[512] | aM[512] | B[512]  -> 1536 uint4 = 24KB
#define STAGE_U4  1536
#define SMEM_BYTES (2 * STAGE_U4 * 16)   // 49152

extern "C" __global__ void __launch_bounds__(TPB, 2)
router_bf16(const float* __restrict__ X, float* __restrict__ out)
{
    extern __shared__ uint4 sm4[];
    const int tid  = threadIdx.x;
    const int wid  = tid >> 5;
    const int lane = tid & 31;
    const int g    = lane >> 2;
    const int t    = lane & 3;
    const int blockM = blockIdx.x * TILE_M;

    if (wid >= 4) {
        // ---------------- producers: warps 4..7 ----------------
        const int p = tid - 128;   // 0..127
        float4 xa[4], xb[4];       // 8 floats per slot
        uint4  bb[4];

        #define PLOAD(c)                                                            \
            {                                                                       \
                _Pragma("unroll")                                                   \
                for (int j = 0; j < 4; j++) {                                       \
                    int s_idx = p + 128 * j;          /* 0..511 */                  \
                    int row = s_idx >> 2, q2 = s_idx & 3;                           \
                    const float* src = X + (size_t)(blockM + row) * KDIM            \
                                         + (c) * KC + q2 * 8;                       \
                    xa[j] = reinterpret_cast<const float4*>(src)[0];                \
                    xb[j] = reinterpret_cast<const float4*>(src)[1];                \
                    bb[j] = g_wperm[(c) * 512 + s_idx];                             \
                }                                                                   \
            }
        #define PSTORE(s)                                                           \
            {                                                                       \
                uint4* aH = sm4 + (s) * STAGE_U4;                                   \
                uint4* aM = aH + 512;                                               \
                uint4* sB = aH + 1024;                                              \
                _Pragma("unroll")                                                   \
                for (int j = 0; j < 4; j++) {                                       \
                    int s_idx = p + 128 * j;                                        \
                    int row = s_idx >> 2, q2 = s_idx & 3;                           \
                    uint4 H, M;                                                     \
                    split_pair(xa[j].x, xa[j].y, H.x, M.x);                         \
                    split_pair(xa[j].z, xa[j].w, H.y, M.y);                         \
                    split_pair(xb[j].x, xb[j].y, H.z, M.z);                         \
                    split_pair(xb[j].z, xb[j].w, H.w, M.w);                         \
                    int a_idx = q2 * 128 + (row ^ (2 * q2));                        \
                    aH[a_idx]  = H;                                                 \
                    aM[a_idx]  = M;                                                 \
                    sB[s_idx]  = bb[j];                                             \
                }                                                                   \
            }

        PLOAD(0);
        PSTORE(0);
        PLOAD(1);
        __syncthreads();

        for (int c = 0; c < NCH; c++) {
            if (c + 1 < NCH) PSTORE((c + 1) & 1);
            if (c + 2 < NCH) PLOAD(c + 2);
            __syncthreads();
        }
        return;
    }

    // ---------------- consumers: warps 0..3, tile m32 x n64 ----------------
    float acc[2][8][4];
    #pragma unroll
    for (int mf = 0; mf < 2; mf++)
        #pragma unroll
        for (int nf = 0; nf < 8; nf++)
            #pragma unroll
            for (int u = 0; u < 4; u++) acc[mf][nf][u] = 0.0f;

    const int wbase = wid * 32;
    __syncthreads();   // match producer prologue

    for (int c = 0; c < NCH; c++) {
        const int s = c & 1;
        const uint32_t* aH = reinterpret_cast<const uint32_t*>(sm4 + s * STAGE_U4);
        const uint32_t* aM = aH + 2048;
        const uint4*    sB = sm4 + s * STAGE_U4 + 1024;

        #pragma unroll
        for (int kb = 0; kb < 2; kb++) {
            uint32_t ah[2][4], am[2][4];
            #pragma unroll
            for (int mf = 0; mf < 2; mf++) {
                const int R0 = wbase + mf * 16 + g;
                // q2 = 2kb (a0,a1), q2 = 2kb+1 (a2,a3); word = uint4_idx*4 + t
                const int i0 = ((2 * kb) * 128 + (R0 ^ (4 * kb))) * 4 + t;
                const int i2 = ((2 * kb + 1) * 128 + (R0 ^ (4 * kb + 2))) * 4 + t;
                ah[mf][0] = aH[i0];       ah[mf][1] = aH[i0 + 32];
                ah[mf][2] = aH[i2];       ah[mf][3] = aH[i2 + 32];
                am[mf][0] = aM[i0];       am[mf][1] = aM[i0 + 32];
                am[mf][2] = aM[i2];       am[mf][3] = aM[i2 + 32];
            }
            #pragma unroll
            for (int nf = 0; nf < 8; nf++) {
                uint4 b = sB[(kb * 8 + nf) * 32 + lane];
                #pragma unroll
                for (int mf = 0; mf < 2; mf++) {
                    mma16(acc[mf][nf], ah[mf], b.x, b.y);   // Ah*Bh
                    mma16(acc[mf][nf], ah[mf], b.z, b.w);   // Ah*Bm
                    mma16(acc[mf][nf], am[mf], b.x, b.y);   // Am*Bh
                }
            }
        }
        __syncthreads();
    }

    // ---------------- epilogue: logits + stable top-2 + softmax ----------------
    float* outIdx = out;
    float* outWgt = out + TOKENS * 2;
    float* outLog = out + TOKENS * 4;

    #pragma unroll
    for (int mf = 0; mf < 2; mf++) {
        #pragma unroll
        for (int h = 0; h < 2; h++) {
            const int row = wbase + mf * 16 + h * 8 + g;
            const int tok = blockM + row;

            float v1 = -INFINITY, v2 = -INFINITY;
            int   i1 = 0, i2 = 0;
            #pragma unroll
            for (int nf = 0; nf < 8; nf++) {
                #pragma unroll
                for (int u = 0; u < 2; u++) {
                    float v  = acc[mf][nf][2 * h + u];
                    int   id = nf * 8 + 2 * t + u;
                    if (v > v1)      { v2 = v1; i2 = i1; v1 = v; i1 = id; }
                    else if (v > v2) { v2 = v;  i2 = id; }
                }
            }
            merge2(v1, i1, v2, i2, 1);
            merge2(v1, i1, v2, i2, 2);

            float* lr = outLog + (size_t)tok * NEXP;
            #pragma unroll
            for (int nf = 0; nf < 8; nf++) {
                float2 o = make_float2(acc[mf][nf][2 * h], acc[mf][nf][2 * h + 1]);
                *reinterpret_cast<float2*>(lr + nf * 8 + 2 * t) = o;
            }

            if (t == 0) {
                float e2  = expf(v2 - v1);          // v1 >= v2 -> stable
                float inv = 1.0f / (1.0f + e2);
                outIdx[tok * 2]     = (float)i1;
                outIdx[tok * 2 + 1] = (float)i2;
                outWgt[tok * 2]     = inv;
                outWgt[tok * 2 + 1] = e2 * inv;
            }
        }
    }
}

extern "C" void kernel_launch(void* const* d_in, const int* in_sizes, int n_in,
                              void* d_out, int out_size)
{
    const float* X = (const float*)d_in[0];   // [32768, 2048] fp32
    const float* W = (const float*)d_in[1];   // [64, 2048] fp32
    float* out = (float*)d_out;

    prep_w<<<128, 256>>>(W);

    cudaFuncSetAttribute(router_bf16,
                         cudaFuncAttributeMaxDynamicSharedMemorySize, SMEM_BYTES);
    router_bf16<<<TOKENS / TILE_M, TPB, SMEM_BYTES>>>(X, out);
}